// round 2
// baseline (speedup 1.0000x reference)
#include <cuda_runtime.h>
#include <cstdint>
#include <math.h>

#define D_MODEL 512
#define N_HEADS 8
#define HEAD_DIM 64
#define BATCH 4
#define SEQ 2048
#define M_TOTAL (BATCH*SEQ)   // 8192

// Scratch (allocation-guard-safe __device__ globals): 4 x 16MB.
// Referenced DIRECTLY from device code — no cudaGetSymbolAddress on host,
// so kernel_launch is pure kernel launches (maximally graph-capturable).
__device__ float g_Q  [BATCH*SEQ*D_MODEL];   // [B,S,D]
__device__ float g_K  [BATCH*SEQ*D_MODEL];   // [B,S,D]
__device__ float g_Vt [BATCH*SEQ*D_MODEL];   // [B,H,hd,SK]  (pre-transposed V)
__device__ float g_ctx[BATCH*SEQ*D_MODEL];   // [B,S,D]

__device__ __forceinline__ uint32_t f2tf(float x){
    uint32_t u; asm("cvt.rna.tf32.f32 %0, %1;" : "=r"(u) : "f"(x)); return u;
}
__device__ __forceinline__ float tf32r(float x){ return __uint_as_float(f2tf(x)); }

__device__ __forceinline__ void mma8(float* d, const uint32_t* a, const uint32_t* b){
    asm volatile(
        "mma.sync.aligned.m16n8k8.row.col.f32.tf32.tf32.f32 "
        "{%0,%1,%2,%3},{%4,%5,%6,%7},{%8,%9},{%0,%1,%2,%3};"
        : "+f"(d[0]), "+f"(d[1]), "+f"(d[2]), "+f"(d[3])
        : "r"(a[0]), "r"(a[1]), "r"(a[2]), "r"(a[3]), "r"(b[0]), "r"(b[1]));
}

__device__ __forceinline__ float gelu_exact(float x){
    return 0.5f * x * (1.0f + erff(x * 0.70710678118654752f));
}

// ---------------------------------------------------------------------------
// GEMM: C[M=8192, 512] = act(A[8192,512]) @ W[512,512]^T + bias
// W row-major [n,k]  ==  col-major B for mma row.col  (both operands K-major)
// MODE 0: A=param, C=g_Q
// MODE 1: A=param, C=g_K
// MODE 2: A=param, C=g_Vt, written transposed as [B, n, SEQ]
// MODE 3: A=g_ctx with exact-erf GELU applied at load, C=param (d_out)
// ---------------------------------------------------------------------------
template<int MODE>
__global__ __launch_bounds__(256) void gemm_kernel(
    const float* __restrict__ Ain, const float* __restrict__ W,
    const float* __restrict__ bias, float* __restrict__ Cout)
{
    constexpr bool TRANS_OUT = (MODE == 2);
    constexpr bool GELU_A    = (MODE == 3);
    const float* __restrict__ A = (MODE == 3) ? (const float*)g_ctx : Ain;
    float* __restrict__ C =
        (MODE == 0) ? (float*)g_Q  :
        (MODE == 1) ? (float*)g_K  :
        (MODE == 2) ? (float*)g_Vt : Cout;

    __shared__ float sA[128][36];   // [m][k] tile, pad->stride 36
    __shared__ float sB[64][36];    // [n][k] tile

    const int tid = threadIdx.x, lane = tid & 31, wrp = tid >> 5;
    const int wm = wrp & 3, wn = wrp >> 2;          // warp grid 4(m) x 2(n)
    const int g = lane >> 2, tg = lane & 3;
    const int m0 = blockIdx.y * 128, n0 = blockIdx.x * 64;

    float acc[2][4][4];
    #pragma unroll
    for (int mi = 0; mi < 2; mi++)
        #pragma unroll
        for (int nj = 0; nj < 4; nj++)
            #pragma unroll
            for (int k = 0; k < 4; k++) acc[mi][nj][k] = 0.f;

    for (int k0 = 0; k0 < D_MODEL; k0 += 32) {
        __syncthreads();
        // A tile: 128x32 = 1024 float4, 256 thr -> 4 each (coalesced rows)
        #pragma unroll
        for (int i = 0; i < 4; i++) {
            int id = tid + i * 256;
            int r = id >> 3, c4 = (id & 7) << 2;
            float4 v = *(const float4*)(A + (size_t)(m0 + r) * D_MODEL + k0 + c4);
            if (GELU_A) {
                v.x = gelu_exact(v.x); v.y = gelu_exact(v.y);
                v.z = gelu_exact(v.z); v.w = gelu_exact(v.w);
            }
            v.x = tf32r(v.x); v.y = tf32r(v.y); v.z = tf32r(v.z); v.w = tf32r(v.w);
            *(float4*)&sA[r][c4] = v;
        }
        // W tile: 64x32 = 512 float4 -> 2 each
        #pragma unroll
        for (int i = 0; i < 2; i++) {
            int id = tid + i * 256;
            int r = id >> 3, c4 = (id & 7) << 2;
            float4 v = *(const float4*)(W + (size_t)(n0 + r) * D_MODEL + k0 + c4);
            v.x = tf32r(v.x); v.y = tf32r(v.y); v.z = tf32r(v.z); v.w = tf32r(v.w);
            *(float4*)&sB[r][c4] = v;
        }
        __syncthreads();
        #pragma unroll
        for (int kk = 0; kk < 4; kk++) {
            uint32_t af[2][4], bf[4][2];
            #pragma unroll
            for (int mi = 0; mi < 2; mi++) {
                int row = wm * 32 + mi * 16;
                af[mi][0] = __float_as_uint(sA[row + g    ][kk * 8 + tg    ]);
                af[mi][1] = __float_as_uint(sA[row + g + 8][kk * 8 + tg    ]);
                af[mi][2] = __float_as_uint(sA[row + g    ][kk * 8 + tg + 4]);
                af[mi][3] = __float_as_uint(sA[row + g + 8][kk * 8 + tg + 4]);
            }
            #pragma unroll
            for (int nj = 0; nj < 4; nj++) {
                int col = wn * 32 + nj * 8;
                bf[nj][0] = __float_as_uint(sB[col + g][kk * 8 + tg    ]);
                bf[nj][1] = __float_as_uint(sB[col + g][kk * 8 + tg + 4]);
            }
            #pragma unroll
            for (int mi = 0; mi < 2; mi++)
                #pragma unroll
                for (int nj = 0; nj < 4; nj++)
                    mma8(acc[mi][nj], af[mi], bf[nj]);
        }
    }

    // Epilogue
    #pragma unroll
    for (int mi = 0; mi < 2; mi++)
        #pragma unroll
        for (int nj = 0; nj < 4; nj++) {
            int col0 = n0 + wn * 32 + nj * 8 + tg * 2;
            float bz0 = bias[col0], bz1 = bias[col0 + 1];
            #pragma unroll
            for (int half = 0; half < 2; half++) {
                int row = m0 + wm * 32 + mi * 16 + g + half * 8;
                float v0 = acc[mi][nj][half * 2 + 0] + bz0;
                float v1 = acc[mi][nj][half * 2 + 1] + bz1;
                if (TRANS_OUT) {
                    int bb = row >> 11, s = row & 2047;   // row = b*2048 + s
                    C[((size_t)(bb * D_MODEL + col0    )) * SEQ + s] = v0;
                    C[((size_t)(bb * D_MODEL + col0 + 1)) * SEQ + s] = v1;
                } else {
                    float2 v; v.x = v0; v.y = v1;
                    *(float2*)&C[(size_t)row * D_MODEL + col0] = v;
                }
            }
        }
}

// ---------------------------------------------------------------------------
// Flash attention: grid (SQ/64, B*H), 128 threads (4 warps; warp owns 16 q rows)
// Reads g_Q [B,S,D] (head slice), g_K [B,S,D], g_Vt [B,H,hd,SK]; writes g_ctx.
// ---------------------------------------------------------------------------
__global__ __launch_bounds__(128) void attn_kernel()
{
    __shared__ float sKP[64][68];   // K tile [kv][d]; reused as P tile [q][kv]
    __shared__ float sV [64][68];   // V^T tile [d][kv]

    const int tid = threadIdx.x, lane = tid & 31, wrp = tid >> 5;
    const int g = lane >> 2, tg = lane & 3;
    const int qb = blockIdx.x, bh = blockIdx.y, b = bh >> 3, h = bh & 7;

    const float* Qp = g_Q + (size_t)(b * SEQ + qb * 64) * D_MODEL + h * HEAD_DIM;
    const float* Kp = g_K + (size_t)b * SEQ * D_MODEL + h * HEAD_DIM;
    const float* Vp = g_Vt + (size_t)bh * HEAD_DIM * SEQ;

    // Q fragments (A-layout), 1/sqrt(hd)=1/8 folded in. Loaded once.
    uint32_t qf[8][4];
    const int qr = wrp * 16 + g;
    #pragma unroll
    for (int kk = 0; kk < 8; kk++) {
        qf[kk][0] = f2tf(Qp[(size_t)(qr    ) * D_MODEL + kk * 8 + tg    ] * 0.125f);
        qf[kk][1] = f2tf(Qp[(size_t)(qr + 8) * D_MODEL + kk * 8 + tg    ] * 0.125f);
        qf[kk][2] = f2tf(Qp[(size_t)(qr    ) * D_MODEL + kk * 8 + tg + 4] * 0.125f);
        qf[kk][3] = f2tf(Qp[(size_t)(qr + 8) * D_MODEL + kk * 8 + tg + 4] * 0.125f);
    }

    float O[8][4];
    #pragma unroll
    for (int j = 0; j < 8; j++)
        #pragma unroll
        for (int k = 0; k < 4; k++) O[j][k] = 0.f;
    float mrow0 = -1e30f, mrow1 = -1e30f, lrow0 = 0.f, lrow1 = 0.f;

    #pragma unroll 1
    for (int t = 0; t < SEQ / 64; t++) {
        __syncthreads();   // previous PV mma done with sKP/sV
        const float* Kt  = Kp + (size_t)t * 64 * D_MODEL;
        const float* Vtt = Vp + t * 64;
        // 64x64 K tile and 64x64 V^T tile: 1024 float4 each, 128 thr -> 8 each
        #pragma unroll
        for (int i = 0; i < 8; i++) {
            int id = tid + i * 128;
            int r = id >> 4, c4 = (id & 15) << 2;
            float4 kv = *(const float4*)(Kt + (size_t)r * D_MODEL + c4);
            kv.x = tf32r(kv.x); kv.y = tf32r(kv.y); kv.z = tf32r(kv.z); kv.w = tf32r(kv.w);
            *(float4*)&sKP[r][c4] = kv;
            float4 vv = *(const float4*)(Vtt + (size_t)r * SEQ + c4);
            vv.x = tf32r(vv.x); vv.y = tf32r(vv.y); vv.z = tf32r(vv.z); vv.w = tf32r(vv.w);
            *(float4*)&sV[r][c4] = vv;
        }
        __syncthreads();

        // S = (Q/8) K^T : warp computes 16 x 64
        float S[8][4];
        #pragma unroll
        for (int j = 0; j < 8; j++)
            #pragma unroll
            for (int k = 0; k < 4; k++) S[j][k] = 0.f;
        #pragma unroll
        for (int kk = 0; kk < 8; kk++) {
            #pragma unroll
            for (int j = 0; j < 8; j++) {
                uint32_t bf[2];
                bf[0] = __float_as_uint(sKP[j * 8 + g][kk * 8 + tg    ]);
                bf[1] = __float_as_uint(sKP[j * 8 + g][kk * 8 + tg + 4]);
                mma8(S[j], qf[kk], bf);
            }
        }

        // online softmax (rows g and g+8; cols partitioned across the quad)
        float tm0 = -1e30f, tm1 = -1e30f;
        #pragma unroll
        for (int j = 0; j < 8; j++) {
            tm0 = fmaxf(tm0, fmaxf(S[j][0], S[j][1]));
            tm1 = fmaxf(tm1, fmaxf(S[j][2], S[j][3]));
        }
        tm0 = fmaxf(tm0, __shfl_xor_sync(0xffffffffu, tm0, 1));
        tm0 = fmaxf(tm0, __shfl_xor_sync(0xffffffffu, tm0, 2));
        tm1 = fmaxf(tm1, __shfl_xor_sync(0xffffffffu, tm1, 1));
        tm1 = fmaxf(tm1, __shfl_xor_sync(0xffffffffu, tm1, 2));
        float mn0 = fmaxf(mrow0, tm0), mn1 = fmaxf(mrow1, tm1);
        float sc0 = __expf(mrow0 - mn0), sc1 = __expf(mrow1 - mn1);
        mrow0 = mn0; mrow1 = mn1;
        float rs0 = 0.f, rs1 = 0.f;
        #pragma unroll
        for (int j = 0; j < 8; j++) {
            S[j][0] = __expf(S[j][0] - mn0); S[j][1] = __expf(S[j][1] - mn0);
            rs0 += S[j][0] + S[j][1];
            S[j][2] = __expf(S[j][2] - mn1); S[j][3] = __expf(S[j][3] - mn1);
            rs1 += S[j][2] + S[j][3];
        }
        lrow0 = lrow0 * sc0 + rs0;
        lrow1 = lrow1 * sc1 + rs1;
        #pragma unroll
        for (int j = 0; j < 8; j++) {
            O[j][0] *= sc0; O[j][1] *= sc0; O[j][2] *= sc1; O[j][3] *= sc1;
        }

        __syncthreads();   // all warps done reading K tile before P overwrites it
        const int pr = wrp * 16 + g;
        #pragma unroll
        for (int j = 0; j < 8; j++) {
            sKP[pr    ][j * 8 + tg * 2    ] = tf32r(S[j][0]);
            sKP[pr    ][j * 8 + tg * 2 + 1] = tf32r(S[j][1]);
            sKP[pr + 8][j * 8 + tg * 2    ] = tf32r(S[j][2]);
            sKP[pr + 8][j * 8 + tg * 2 + 1] = tf32r(S[j][3]);
        }
        __syncwarp();      // warp reads back only its own 16 rows

        // O += P V : A = P (q x kv), B = V (kv x d) via sV = V^T
        #pragma unroll
        for (int kk = 0; kk < 8; kk++) {
            uint32_t pa[4];
            pa[0] = __float_as_uint(sKP[pr    ][kk * 8 + tg    ]);
            pa[1] = __float_as_uint(sKP[pr + 8][kk * 8 + tg    ]);
            pa[2] = __float_as_uint(sKP[pr    ][kk * 8 + tg + 4]);
            pa[3] = __float_as_uint(sKP[pr + 8][kk * 8 + tg + 4]);
            #pragma unroll
            for (int j = 0; j < 8; j++) {
                uint32_t bf[2];
                bf[0] = __float_as_uint(sV[j * 8 + g][kk * 8 + tg    ]);
                bf[1] = __float_as_uint(sV[j * 8 + g][kk * 8 + tg + 4]);
                mma8(O[j], pa, bf);
            }
        }
    }

    // finalize: row sums across quad, normalize, write ctx
    lrow0 += __shfl_xor_sync(0xffffffffu, lrow0, 1);
    lrow0 += __shfl_xor_sync(0xffffffffu, lrow0, 2);
    lrow1 += __shfl_xor_sync(0xffffffffu, lrow1, 1);
    lrow1 += __shfl_xor_sync(0xffffffffu, lrow1, 2);
    float inv0 = 1.f / lrow0, inv1 = 1.f / lrow1;

    const int r0 = b * SEQ + qb * 64 + wrp * 16 + g;
    #pragma unroll
    for (int j = 0; j < 8; j++) {
        int col = h * HEAD_DIM + j * 8 + tg * 2;
        float2 v0; v0.x = O[j][0] * inv0; v0.y = O[j][1] * inv0;
        float2 v1; v1.x = O[j][2] * inv1; v1.y = O[j][3] * inv1;
        *(float2*)&g_ctx[(size_t)(r0    ) * D_MODEL + col] = v0;
        *(float2*)&g_ctx[(size_t)(r0 + 8) * D_MODEL + col] = v1;
    }
}

// ---------------------------------------------------------------------------
extern "C" void kernel_launch(void* const* d_in, const int* in_sizes, int n_in,
                              void* d_out, int out_size)
{
    const float* query = (const float*)d_in[0];
    const float* key   = (const float*)d_in[1];
    const float* value = (const float*)d_in[2];
    const float* Wq    = (const float*)d_in[3];
    const float* bq    = (const float*)d_in[4];
    const float* Wk    = (const float*)d_in[5];
    const float* bk    = (const float*)d_in[6];
    const float* Wv    = (const float*)d_in[7];
    const float* bv    = (const float*)d_in[8];
    const float* Wo    = (const float*)d_in[9];
    const float* bo    = (const float*)d_in[10];
    float* out = (float*)d_out;

    dim3 gg(D_MODEL / 64, M_TOTAL / 128);
    gemm_kernel<0><<<gg, 256>>>(query, Wq, bq, nullptr);
    gemm_kernel<1><<<gg, 256>>>(key,   Wk, bk, nullptr);
    gemm_kernel<2><<<gg, 256>>>(value, Wv, bv, nullptr);
    attn_kernel<<<dim3(SEQ / 64, BATCH * N_HEADS), 128>>>();
    gemm_kernel<3><<<gg, 256>>>(nullptr, Wo, bo, out);
}

// round 3
// speedup vs baseline: 1.7750x; 1.7750x over previous
#include <cuda_runtime.h>
#include <cuda_fp16.h>
#include <cstdint>
#include <math.h>

#define D_MODEL 512
#define N_HEADS 8
#define HEAD_DIM 64
#define BATCH 4
#define SEQ 2048
#define M_TOTAL (BATCH*SEQ)   // 8192

// Scratch: __device__ globals (allocation-guard-safe), referenced directly
// from device code. Q/K/Vt are fp16 (written by projections), ctx is fp32.
__device__ __half g_Q  [BATCH*SEQ*D_MODEL];   // [B,S,D]   pre-scaled by 1/8
__device__ __half g_K  [BATCH*SEQ*D_MODEL];   // [B,S,D]
__device__ __half g_Vt [BATCH*SEQ*D_MODEL];   // [B,H,hd,SK] (pre-transposed V)
__device__ float  g_ctx[BATCH*SEQ*D_MODEL];   // [B,S,D]

__device__ __forceinline__ void mma16(float* d, const uint32_t* a, const uint32_t* b){
    asm volatile(
        "mma.sync.aligned.m16n8k16.row.col.f32.f16.f16.f32 "
        "{%0,%1,%2,%3},{%4,%5,%6,%7},{%8,%9},{%0,%1,%2,%3};"
        : "+f"(d[0]), "+f"(d[1]), "+f"(d[2]), "+f"(d[3])
        : "r"(a[0]), "r"(a[1]), "r"(a[2]), "r"(a[3]), "r"(b[0]), "r"(b[1]));
}

__device__ __forceinline__ float gelu_exact(float x){
    return 0.5f * x * (1.0f + erff(x * 0.70710678118654752f));
}

// ---------------------------------------------------------------------------
// GEMM: C[8192,512] = act(A[8192,512]) @ W[512,512]^T + bias   (fp16 mma)
// MODE 0: C=g_Q  fp16, result scaled by 1/8 (attention score scale folded in)
// MODE 1: C=g_K  fp16
// MODE 2: C=g_Vt fp16, written transposed as [B, n, SEQ]
// MODE 3: A=g_ctx with exact-erf GELU at load; C=param fp32 (d_out)
// Tile 128x64, k-tile 64, 256 threads, warp grid 4(m) x 2(n), warp tile 32x32.
// ---------------------------------------------------------------------------
template<int MODE>
__global__ __launch_bounds__(256) void gemm_kernel(
    const float* __restrict__ Ain, const float* __restrict__ W,
    const float* __restrict__ bias, float* __restrict__ Cout)
{
    const float* __restrict__ A = (MODE == 3) ? (const float*)g_ctx : Ain;

    __shared__ __half sA[128][72];   // [m][k], pitch 72 halves (36 words)
    __shared__ __half sB[64][72];    // [n][k]

    const int tid = threadIdx.x, lane = tid & 31, wrp = tid >> 5;
    const int wm = wrp & 3, wn = wrp >> 2;
    const int g = lane >> 2, tg = lane & 3;
    const int m0 = blockIdx.y * 128, n0 = blockIdx.x * 64;

    float acc[2][4][4];
    #pragma unroll
    for (int mi = 0; mi < 2; mi++)
        #pragma unroll
        for (int nj = 0; nj < 4; nj++)
            #pragma unroll
            for (int k = 0; k < 4; k++) acc[mi][nj][k] = 0.f;

    float4 pa[8], pb[4];
    // load tile 0
    #pragma unroll
    for (int i = 0; i < 8; i++) {
        int id = tid + i * 256, r = id >> 4, c4 = (id & 15) << 2;
        pa[i] = *(const float4*)(A + (size_t)(m0 + r) * D_MODEL + c4);
    }
    #pragma unroll
    for (int i = 0; i < 4; i++) {
        int id = tid + i * 256, r = id >> 4, c4 = (id & 15) << 2;
        pb[i] = *(const float4*)(W + (size_t)(n0 + r) * D_MODEL + c4);
    }

    for (int it = 0; it < 8; it++) {
        __syncthreads();   // previous compute done with smem
        #pragma unroll
        for (int i = 0; i < 8; i++) {
            int id = tid + i * 256, r = id >> 4, c4 = (id & 15) << 2;
            float4 v = pa[i];
            if (MODE == 3) {
                v.x = gelu_exact(v.x); v.y = gelu_exact(v.y);
                v.z = gelu_exact(v.z); v.w = gelu_exact(v.w);
            }
            *(__half2*)&sA[r][c4]     = __floats2half2_rn(v.x, v.y);
            *(__half2*)&sA[r][c4 + 2] = __floats2half2_rn(v.z, v.w);
        }
        #pragma unroll
        for (int i = 0; i < 4; i++) {
            int id = tid + i * 256, r = id >> 4, c4 = (id & 15) << 2;
            float4 v = pb[i];
            *(__half2*)&sB[r][c4]     = __floats2half2_rn(v.x, v.y);
            *(__half2*)&sB[r][c4 + 2] = __floats2half2_rn(v.z, v.w);
        }
        __syncthreads();

        if (it < 7) {   // issue next-tile loads before compute (overlap)
            int k0 = (it + 1) * 64;
            #pragma unroll
            for (int i = 0; i < 8; i++) {
                int id = tid + i * 256, r = id >> 4, c4 = (id & 15) << 2;
                pa[i] = *(const float4*)(A + (size_t)(m0 + r) * D_MODEL + k0 + c4);
            }
            #pragma unroll
            for (int i = 0; i < 4; i++) {
                int id = tid + i * 256, r = id >> 4, c4 = (id & 15) << 2;
                pb[i] = *(const float4*)(W + (size_t)(n0 + r) * D_MODEL + k0 + c4);
            }
        }

        #pragma unroll
        for (int kk = 0; kk < 4; kk++) {
            uint32_t af[2][4], bf[4][2];
            #pragma unroll
            for (int mi = 0; mi < 2; mi++) {
                int row = wm * 32 + mi * 16 + g;
                const uint32_t* r0 = (const uint32_t*)&sA[row][0];
                const uint32_t* r1 = (const uint32_t*)&sA[row + 8][0];
                af[mi][0] = r0[kk * 8 + tg];     af[mi][1] = r1[kk * 8 + tg];
                af[mi][2] = r0[kk * 8 + tg + 4]; af[mi][3] = r1[kk * 8 + tg + 4];
            }
            #pragma unroll
            for (int nj = 0; nj < 4; nj++) {
                const uint32_t* rb = (const uint32_t*)&sB[wn * 32 + nj * 8 + g][0];
                bf[nj][0] = rb[kk * 8 + tg]; bf[nj][1] = rb[kk * 8 + tg + 4];
            }
            #pragma unroll
            for (int mi = 0; mi < 2; mi++)
                #pragma unroll
                for (int nj = 0; nj < 4; nj++)
                    mma16(acc[mi][nj], af[mi], bf[nj]);
        }
    }

    // Epilogue
    #pragma unroll
    for (int mi = 0; mi < 2; mi++)
        #pragma unroll
        for (int nj = 0; nj < 4; nj++) {
            int col0 = n0 + wn * 32 + nj * 8 + tg * 2;
            float bz0 = bias[col0], bz1 = bias[col0 + 1];
            #pragma unroll
            for (int half = 0; half < 2; half++) {
                int row = m0 + wm * 32 + mi * 16 + g + half * 8;
                float v0 = acc[mi][nj][half * 2 + 0] + bz0;
                float v1 = acc[mi][nj][half * 2 + 1] + bz1;
                if (MODE == 0) { v0 *= 0.125f; v1 *= 0.125f; }
                if (MODE == 0) {
                    *(__half2*)&g_Q[(size_t)row * D_MODEL + col0] = __floats2half2_rn(v0, v1);
                } else if (MODE == 1) {
                    *(__half2*)&g_K[(size_t)row * D_MODEL + col0] = __floats2half2_rn(v0, v1);
                } else if (MODE == 2) {
                    int bb = row >> 11, s = row & 2047;
                    g_Vt[((size_t)(bb * D_MODEL + col0    )) * SEQ + s] = __float2half_rn(v0);
                    g_Vt[((size_t)(bb * D_MODEL + col0 + 1)) * SEQ + s] = __float2half_rn(v1);
                } else {
                    float2 v; v.x = v0; v.y = v1;
                    *(float2*)&Cout[(size_t)row * D_MODEL + col0] = v;
                }
            }
        }
}

// ---------------------------------------------------------------------------
// Flash attention (fp16 mma): grid (SQ/64, B*H), 128 threads, warp = 16 q rows.
// g_Q pre-scaled by 1/8.  K tile [kv][d], V^T tile [d][kv], P reuses K tile.
// ---------------------------------------------------------------------------
__global__ __launch_bounds__(128) void attn_kernel()
{
    __shared__ __half sKP[64][72];   // K tile [kv][d]; reused as P tile [q][kv]
    __shared__ __half sV [64][72];   // V^T tile [d][kv]

    const int tid = threadIdx.x, lane = tid & 31, wrp = tid >> 5;
    const int g = lane >> 2, tg = lane & 3;
    const int qb = blockIdx.x, bh = blockIdx.y, b = bh >> 3, h = bh & 7;

    const __half* Qp = g_Q + (size_t)(b * SEQ + qb * 64) * D_MODEL + h * HEAD_DIM;
    const __half* Kp = g_K + (size_t)b * SEQ * D_MODEL + h * HEAD_DIM;
    const __half* Vp = g_Vt + (size_t)bh * HEAD_DIM * SEQ;

    // Q fragments (A-layout, fp16 pairs), loaded once: 16 regs
    uint32_t qf[4][4];
    const int qr = wrp * 16 + g;
    {
        const uint32_t* q0 = (const uint32_t*)(Qp + (size_t)qr * D_MODEL);
        const uint32_t* q1 = (const uint32_t*)(Qp + (size_t)(qr + 8) * D_MODEL);
        #pragma unroll
        for (int kk = 0; kk < 4; kk++) {
            qf[kk][0] = q0[kk * 8 + tg];     qf[kk][1] = q1[kk * 8 + tg];
            qf[kk][2] = q0[kk * 8 + tg + 4]; qf[kk][3] = q1[kk * 8 + tg + 4];
        }
    }

    float O[8][4];
    #pragma unroll
    for (int j = 0; j < 8; j++)
        #pragma unroll
        for (int k = 0; k < 4; k++) O[j][k] = 0.f;
    float mrow0 = -1e30f, mrow1 = -1e30f, lrow0 = 0.f, lrow1 = 0.f;

    #pragma unroll 1
    for (int t = 0; t < SEQ / 64; t++) {
        __syncthreads();   // previous PV mma done with sKP/sV
        const __half* Kt  = Kp + (size_t)t * 64 * D_MODEL;
        const __half* Vtt = Vp + t * 64;
        // 64x64 fp16 tiles: 512 uint4 each, 128 thr -> 4 each
        #pragma unroll
        for (int i = 0; i < 4; i++) {
            int id = tid + i * 128;
            int r = id >> 3, c = (id & 7) << 3;
            *(uint4*)&sKP[r][c] = *(const uint4*)(Kt + (size_t)r * D_MODEL + c);
            *(uint4*)&sV[r][c]  = *(const uint4*)(Vtt + (size_t)r * SEQ + c);
        }
        __syncthreads();

        // S = Q' K^T : warp computes 16 x 64 (4 k-steps of 16)
        float S[8][4];
        #pragma unroll
        for (int j = 0; j < 8; j++)
            #pragma unroll
            for (int k = 0; k < 4; k++) S[j][k] = 0.f;
        #pragma unroll
        for (int kk = 0; kk < 4; kk++) {
            #pragma unroll
            for (int j = 0; j < 8; j++) {
                const uint32_t* rb = (const uint32_t*)&sKP[j * 8 + g][0];
                uint32_t bf[2];
                bf[0] = rb[kk * 8 + tg]; bf[1] = rb[kk * 8 + tg + 4];
                mma16(S[j], qf[kk], bf);
            }
        }

        // online softmax (rows g, g+8; cols partitioned across the quad)
        float tm0 = -1e30f, tm1 = -1e30f;
        #pragma unroll
        for (int j = 0; j < 8; j++) {
            tm0 = fmaxf(tm0, fmaxf(S[j][0], S[j][1]));
            tm1 = fmaxf(tm1, fmaxf(S[j][2], S[j][3]));
        }
        tm0 = fmaxf(tm0, __shfl_xor_sync(0xffffffffu, tm0, 1));
        tm0 = fmaxf(tm0, __shfl_xor_sync(0xffffffffu, tm0, 2));
        tm1 = fmaxf(tm1, __shfl_xor_sync(0xffffffffu, tm1, 1));
        tm1 = fmaxf(tm1, __shfl_xor_sync(0xffffffffu, tm1, 2));
        float mn0 = fmaxf(mrow0, tm0), mn1 = fmaxf(mrow1, tm1);
        float sc0 = __expf(mrow0 - mn0), sc1 = __expf(mrow1 - mn1);
        mrow0 = mn0; mrow1 = mn1;
        float rs0 = 0.f, rs1 = 0.f;
        #pragma unroll
        for (int j = 0; j < 8; j++) {
            S[j][0] = __expf(S[j][0] - mn0); S[j][1] = __expf(S[j][1] - mn0);
            rs0 += S[j][0] + S[j][1];
            S[j][2] = __expf(S[j][2] - mn1); S[j][3] = __expf(S[j][3] - mn1);
            rs1 += S[j][2] + S[j][3];
        }
        lrow0 = lrow0 * sc0 + rs0;
        lrow1 = lrow1 * sc1 + rs1;
        #pragma unroll
        for (int j = 0; j < 8; j++) {
            O[j][0] *= sc0; O[j][1] *= sc0; O[j][2] *= sc1; O[j][3] *= sc1;
        }

        __syncthreads();   // all warps done reading K tile before P overwrites it
        const int pr = wrp * 16 + g;
        #pragma unroll
        for (int j = 0; j < 8; j++) {
            *(__half2*)&sKP[pr    ][j * 8 + tg * 2] = __floats2half2_rn(S[j][0], S[j][1]);
            *(__half2*)&sKP[pr + 8][j * 8 + tg * 2] = __floats2half2_rn(S[j][2], S[j][3]);
        }
        __syncwarp();      // warp reads back only its own 16 rows

        // O += P V  (4 kv k-steps of 16)
        #pragma unroll
        for (int kk = 0; kk < 4; kk++) {
            const uint32_t* p0 = (const uint32_t*)&sKP[pr][0];
            const uint32_t* p1 = (const uint32_t*)&sKP[pr + 8][0];
            uint32_t pa[4];
            pa[0] = p0[kk * 8 + tg];     pa[1] = p1[kk * 8 + tg];
            pa[2] = p0[kk * 8 + tg + 4]; pa[3] = p1[kk * 8 + tg + 4];
            #pragma unroll
            for (int j = 0; j < 8; j++) {
                const uint32_t* rb = (const uint32_t*)&sV[j * 8 + g][0];
                uint32_t bf[2];
                bf[0] = rb[kk * 8 + tg]; bf[1] = rb[kk * 8 + tg + 4];
                mma16(O[j], pa, bf);
            }
        }
    }

    // finalize: row sums across quad, normalize, write ctx (fp32)
    lrow0 += __shfl_xor_sync(0xffffffffu, lrow0, 1);
    lrow0 += __shfl_xor_sync(0xffffffffu, lrow0, 2);
    lrow1 += __shfl_xor_sync(0xffffffffu, lrow1, 1);
    lrow1 += __shfl_xor_sync(0xffffffffu, lrow1, 2);
    float inv0 = 1.f / lrow0, inv1 = 1.f / lrow1;

    const int r0 = b * SEQ + qb * 64 + wrp * 16 + g;
    #pragma unroll
    for (int j = 0; j < 8; j++) {
        int col = h * HEAD_DIM + j * 8 + tg * 2;
        float2 v0; v0.x = O[j][0] * inv0; v0.y = O[j][1] * inv0;
        float2 v1; v1.x = O[j][2] * inv1; v1.y = O[j][3] * inv1;
        *(float2*)&g_ctx[(size_t)(r0    ) * D_MODEL + col] = v0;
        *(float2*)&g_ctx[(size_t)(r0 + 8) * D_MODEL + col] = v1;
    }
}

// ---------------------------------------------------------------------------
extern "C" void kernel_launch(void* const* d_in, const int* in_sizes, int n_in,
                              void* d_out, int out_size)
{
    const float* query = (const float*)d_in[0];
    const float* key   = (const float*)d_in[1];
    const float* value = (const float*)d_in[2];
    const float* Wq    = (const float*)d_in[3];
    const float* bq    = (const float*)d_in[4];
    const float* Wk    = (const float*)d_in[5];
    const float* bk    = (const float*)d_in[6];
    const float* Wv    = (const float*)d_in[7];
    const float* bv    = (const float*)d_in[8];
    const float* Wo    = (const float*)d_in[9];
    const float* bo    = (const float*)d_in[10];
    float* out = (float*)d_out;

    dim3 gg(D_MODEL / 64, M_TOTAL / 128);
    gemm_kernel<0><<<gg, 256>>>(query, Wq, bq, nullptr);
    gemm_kernel<1><<<gg, 256>>>(key,   Wk, bk, nullptr);
    gemm_kernel<2><<<gg, 256>>>(value, Wv, bv, nullptr);
    attn_kernel<<<dim3(SEQ / 64, BATCH * N_HEADS), 128>>>();
    gemm_kernel<3><<<gg, 256>>>(nullptr, Wo, bo, out);
}